// round 15
// baseline (speedup 1.0000x reference)
#include <cuda_runtime.h>

#define NN 512
#define BB 2
#define OO 16
#define CHN 48
#define H1DIM 514
#define SKIP_OFF (512*512*2*16)
#define RPB 128
#define PITCH 132
#define NBLK 2052

typedef unsigned long long ull;

// ---------------- packed f32x2 helpers (Blackwell FFMA2 via PTX) ----------------
__device__ __forceinline__ ull pk2(float lo, float hi){
    ull r; asm("mov.b64 %0, {%1,%2};" : "=l"(r) : "f"(lo), "f"(hi)); return r;
}
__device__ __forceinline__ ull dup2(float v){ return pk2(v, v); }
__device__ __forceinline__ float2 upk2(ull p){
    float2 r; asm("mov.b64 {%0,%1}, %2;" : "=f"(r.x), "=f"(r.y) : "l"(p)); return r;
}
__device__ __forceinline__ void fma2(ull &d, ull a, ull b){
    asm("fma.rn.f32x2 %0, %1, %2, %0;" : "+l"(d) : "l"(a), "l"(b));
}

// ---------------- scratch ----------------
__device__ __align__(16) float g_xc[513*256];
__device__ __align__(16) float g_x2c[513*256];
__device__ __align__(16) float g_x3c[513*256];
__device__ __align__(16) float g_w1T[768*64];
__device__ __align__(16) float g_w2T[64*64];
__device__ __align__(16) float g_w3T[64*16];
__device__ __align__(16) float g_sw1T[384*64];
__device__ __align__(16) float g_sw2T[64*64];
__device__ __align__(16) float g_sw3T[64*16];
__device__ __align__(16) float g_cw1T[16*9*48];
__device__ __align__(16) float g_cw2T[48*9*16];
__device__ __align__(16) float g_A[1024*64];
__device__ __align__(16) float g_Bv[1024*64];
__device__ __align__(16) float g_M[1026*64];
__device__ __align__(16) float g_Kc[16];
__device__ __align__(16) float g_S[BB*OO*NN*NN];
__device__ __align__(16) float g_H1[BB*CHN*H1DIM*H1DIM];

__device__ __forceinline__ float gelu(float v){
    return 0.5f*v*(1.0f + erff(0.70710678118654752440f*v));
}

// ---------------- init: 8 weight transposes + moment prefix sums, one kernel ----------------
__global__ void k_init(const float* __restrict__ w1,  const float* __restrict__ w2,
                       const float* __restrict__ w3,  const float* __restrict__ sw1,
                       const float* __restrict__ sw2, const float* __restrict__ sw3,
                       const float* __restrict__ cw1, const float* __restrict__ cw2,
                       const float* __restrict__ x){
    if (blockIdx.y == 8){
        if (blockIdx.x != 0) return;
        int col = threadIdx.x;
        float c1 = 0.f, c2 = 0.f, c3 = 0.f;
        g_xc[col] = 0.f; g_x2c[col] = 0.f; g_x3c[col] = 0.f;
        for (int n0 = 0; n0 < NN; n0 += 8){
            float buf[8];
            #pragma unroll
            for (int u = 0; u < 8; u++) buf[u] = x[(n0+u)*256 + col];
            #pragma unroll
            for (int u = 0; u < 8; u++){
                float v = buf[u];
                c1 += v; c2 += v*v; c3 += v*v*v;
                int r = (n0+u+1)*256 + col;
                g_xc[r] = c1; g_x2c[r] = c2; g_x3c[r] = c3;
            }
        }
        return;
    }
    const float* src; float* dst; int Osz, Ksz;
    switch(blockIdx.y){
        case 0: src = w1;  dst = g_w1T;  Osz = 64; Ksz = 768; break;
        case 1: src = w2;  dst = g_w2T;  Osz = 64; Ksz = 64;  break;
        case 2: src = w3;  dst = g_w3T;  Osz = 16; Ksz = 64;  break;
        case 3: src = sw1; dst = g_sw1T; Osz = 64; Ksz = 384; break;
        case 4: src = sw2; dst = g_sw2T; Osz = 64; Ksz = 64;  break;
        case 5: src = sw3; dst = g_sw3T; Osz = 16; Ksz = 64;  break;
        case 6: src = cw1; dst = g_cw1T; Osz = 48; Ksz = 144; break;
        default:src = cw2; dst = g_cw2T; Osz = 16; Ksz = 432; break;
    }
    int idx = blockIdx.x*blockDim.x + threadIdx.x;
    if (idx < Osz*Ksz){
        int o = idx / Ksz, k = idx - o*Ksz;
        dst[k*Osz + o] = src[idx];
    }
}

// ---------------- separable layer-1 precomputes + fused S-zeroing + Kc ----------------
#define ZGRID 2048
__global__ void k_precompute(const float* __restrict__ x, const float* __restrict__ b1,
                             const float* __restrict__ cb1, const float* __restrict__ cb2,
                             const float* __restrict__ cw2){
    int type = blockIdx.y;
    int rid  = blockIdx.x;
    int t    = threadIdx.x;
    if (rid >= 1026){
        int zid = ((rid-1026)*3 + type)*64 + t;
        const int total4 = BB*OO*NN*NN/4;
        for (int i = zid; i < total4; i += ZGRID*3*64)
            ((float4*)g_S)[i] = make_float4(0.f,0.f,0.f,0.f);
        if (type == 2 && rid == 1026 && t < 16){
            float kc = cb2[t];
            for (int ic = 0; ic < 48; ic++){
                float c1v = gelu(cb1[ic]);
                #pragma unroll
                for (int k = 0; k < 9; k++)
                    kc += cw2[t*432 + ic*9 + k] * c1v;
            }
            g_Kc[t] = kc;
        }
        return;
    }
    __shared__ float sIn[384];
    if (type < 2){
        if (rid >= 1024) return;
        const float* xr = x + rid*128;
        sIn[t] = xr[t]; sIn[64+t] = xr[64+t];
        __syncthreads();
        float acc = (type == 0) ? b1[t] : 0.f;
        const float* w = g_w1T + (type == 0 ? 0 : 128)*64 + t;
        #pragma unroll 4
        for (int d = 0; d < 128; d++) acc += sIn[d] * w[d*64];
        (type == 0 ? g_A : g_Bv)[rid*64 + t] = acc;
    } else {
        const float* c1 = g_xc  + rid*128;
        const float* c2 = g_x2c + rid*128;
        const float* c3 = g_x3c + rid*128;
        sIn[t]       = c1[t]; sIn[64+t]  = c1[64+t];
        sIn[128+t]   = c2[t]; sIn[192+t] = c2[64+t];
        sIn[256+t]   = c3[t]; sIn[320+t] = c3[64+t];
        __syncthreads();
        float acc = 0.f;
        #pragma unroll 4
        for (int d = 0; d < 128; d++){
            acc += sIn[d]       * g_w1T[(384+d)*64 + t];
            acc += sIn[128 + d] * g_w1T[(512+d)*64 + t];
            acc += sIn[256 + d] * g_w1T[(640+d)*64 + t];
        }
        g_M[rid*64 + t] = acc;
    }
}

// ---------------- pair MLP: 128x64 tile, 128 threads, 8x8 per thread ----------------
#define MMA_STEP(kk, k2) { \
    ulonglong2 a01 = *(const ulonglong2*)&sA[(kk)*PITCH + tr*8]; \
    ulonglong2 a23 = *(const ulonglong2*)&sA[(kk)*PITCH + tr*8 + 4]; \
    float4 b0 = *(const float4*)&sB[(k2)*64 + tc*8]; \
    float4 b1 = *(const float4*)&sB[(k2)*64 + tc*8 + 4]; \
    ull u0=dup2(b0.x),u1=dup2(b0.y),u2=dup2(b0.z),u3=dup2(b0.w); \
    ull u4=dup2(b1.x),u5=dup2(b1.y),u6=dup2(b1.z),u7=dup2(b1.w); \
    fma2(acc[0][0],a01.x,u0); fma2(acc[0][1],a01.x,u1); fma2(acc[0][2],a01.x,u2); fma2(acc[0][3],a01.x,u3); \
    fma2(acc[0][4],a01.x,u4); fma2(acc[0][5],a01.x,u5); fma2(acc[0][6],a01.x,u6); fma2(acc[0][7],a01.x,u7); \
    fma2(acc[1][0],a01.y,u0); fma2(acc[1][1],a01.y,u1); fma2(acc[1][2],a01.y,u2); fma2(acc[1][3],a01.y,u3); \
    fma2(acc[1][4],a01.y,u4); fma2(acc[1][5],a01.y,u5); fma2(acc[1][6],a01.y,u6); fma2(acc[1][7],a01.y,u7); \
    fma2(acc[2][0],a23.x,u0); fma2(acc[2][1],a23.x,u1); fma2(acc[2][2],a23.x,u2); fma2(acc[2][3],a23.x,u3); \
    fma2(acc[2][4],a23.x,u4); fma2(acc[2][5],a23.x,u5); fma2(acc[2][6],a23.x,u6); fma2(acc[2][7],a23.x,u7); \
    fma2(acc[3][0],a23.y,u0); fma2(acc[3][1],a23.y,u1); fma2(acc[3][2],a23.y,u2); fma2(acc[3][3],a23.y,u3); \
    fma2(acc[3][4],a23.y,u4); fma2(acc[3][5],a23.y,u5); fma2(acc[3][6],a23.y,u6); fma2(acc[3][7],a23.y,u7); \
}

__global__ void __launch_bounds__(128) k_pair(const float* __restrict__ x,
                                              const float* __restrict__ b2,
                                              const float* __restrict__ b3){
    __shared__ __align__(16) float sA[64*PITCH];   // [k][row]  33.8KB
    __shared__ __align__(16) float sB[32*64];      // weight sub-chunk 8KB
    __shared__ int   sI[RPB], sJ[RPB];
    __shared__ float sInvL[RPB];

    int tid  = threadIdx.x;
    int base = blockIdx.x * RPB;

    {
        int m = base + tid;
        int p = m >> 1;
        int i = (int)floorf((sqrtf(8.0f*(float)p + 1.0f) - 1.0f) * 0.5f);
        while ((i+1)*(i+2)/2 <= p) i++;
        while (i*(i+1)/2 > p)      i--;
        int j = p - i*(i+1)/2;
        sI[tid] = i; sJ[tid] = j;
        sInvL[tid] = 1.0f / (float)(i - j + 1);
    }
    __syncthreads();

    int tr = tid >> 3, tc = tid & 7;   // rows tr*8..+7, cols tc*8..+7
    ull acc[4][8];
    #pragma unroll
    for (int a = 0; a < 4; a++)
        #pragma unroll
        for (int c = 0; c < 8; c++) acc[a][c] = 0ull;

    int sbb = (base + tid) & 1;
    const float* xi = x + (sI[tid]*2 + sbb)*128;
    const float* xj = x + (sJ[tid]*2 + sbb)*128;

    // ---- layer 1: pairwise curA*curB segment, K=128 (2 chunks of 64) ----
    for (int kc = 0; kc < 2; kc++){
        if (kc) __syncthreads();
        #pragma unroll
        for (int q = 0; q < 16; q++){
            int dd = kc*64 + q*4;
            float4 a4 = *(const float4*)(xi + dd);
            float4 c4 = *(const float4*)(xj + dd);
            sA[(q*4+0)*PITCH + tid] = a4.x*c4.x;
            sA[(q*4+1)*PITCH + tid] = a4.y*c4.y;
            sA[(q*4+2)*PITCH + tid] = a4.z*c4.z;
            sA[(q*4+3)*PITCH + tid] = a4.w*c4.w;
        }
        for (int sub = 0; sub < 2; sub++){
            __syncthreads();
            {
                const float4* src = (const float4*)(g_w1T + (256 + kc*64 + sub*32)*64);
                #pragma unroll
                for (int q = 0; q < 4; q++)
                    ((float4*)sB)[q*128 + tid] = src[q*128 + tid];
            }
            __syncthreads();
            #pragma unroll 2
            for (int k2 = 0; k2 < 32; k2++){
                int kk = sub*32 + k2;
                MMA_STEP(kk, k2)
            }
        }
    }
    __syncthreads();

    // ---- epilogue L1: + separable pre, gelu, write h1 as f32x2 row-pairs ----
    #pragma unroll
    for (int rp = 0; rp < 4; rp++){
        int r0 = tr*8 + 2*rp;
        float vout[2][8];
        #pragma unroll
        for (int lane = 0; lane < 2; lane++){
            int r = r0 + lane;
            int ii = sI[r], jj = sJ[r];
            int bb2 = (base + r) & 1;
            float il = sInvL[r];
            const float* pA  = g_A  + (ii*2+bb2)*64 + tc*8;
            const float* pB  = g_Bv + (jj*2+bb2)*64 + tc*8;
            const float* pM1 = g_M  + ((ii+1)*2+bb2)*64 + tc*8;
            const float* pM0 = g_M  + (jj*2+bb2)*64 + tc*8;
            #pragma unroll
            for (int h = 0; h < 2; h++){
                float4 pa = *(const float4*)(pA  + 4*h);
                float4 pb = *(const float4*)(pB  + 4*h);
                float4 m1 = *(const float4*)(pM1 + 4*h);
                float4 m0 = *(const float4*)(pM0 + 4*h);
                float2 q0 = upk2(acc[rp][4*h+0]);
                float2 q1 = upk2(acc[rp][4*h+1]);
                float2 q2 = upk2(acc[rp][4*h+2]);
                float2 q3 = upk2(acc[rp][4*h+3]);
                vout[lane][4*h+0] = gelu((lane?q0.y:q0.x) + pa.x + pb.x + il*(m1.x-m0.x));
                vout[lane][4*h+1] = gelu((lane?q1.y:q1.x) + pa.y + pb.y + il*(m1.y-m0.y));
                vout[lane][4*h+2] = gelu((lane?q2.y:q2.x) + pa.z + pb.z + il*(m1.z-m0.z));
                vout[lane][4*h+3] = gelu((lane?q3.y:q3.x) + pa.w + pb.w + il*(m1.w-m0.w));
            }
        }
        #pragma unroll
        for (int c = 0; c < 8; c++){
            *(ull*)&sA[(tc*8+c)*PITCH + r0] = pk2(vout[0][c], vout[1][c]);
            acc[rp][c] = 0ull;
        }
    }

    // ---- layer 2 (K=64, 2 sub-chunks) ----
    for (int sub = 0; sub < 2; sub++){
        __syncthreads();
        {
            const float4* src = (const float4*)(g_w2T + sub*32*64);
            #pragma unroll
            for (int q = 0; q < 4; q++)
                ((float4*)sB)[q*128 + tid] = src[q*128 + tid];
        }
        __syncthreads();
        #pragma unroll 2
        for (int k2 = 0; k2 < 32; k2++){
            int kk = sub*32 + k2;
            MMA_STEP(kk, k2)
        }
    }
    __syncthreads();

    // ---- epilogue L2: +b2, gelu, write h2; stage w3 ----
    {
        float4 bv0 = *(const float4*)(b2 + tc*8);
        float4 bv1 = *(const float4*)(b2 + tc*8 + 4);
        float bv[8] = {bv0.x,bv0.y,bv0.z,bv0.w,bv1.x,bv1.y,bv1.z,bv1.w};
        #pragma unroll
        for (int rp = 0; rp < 4; rp++){
            int r0 = tr*8 + 2*rp;
            #pragma unroll
            for (int c = 0; c < 8; c++){
                float2 q = upk2(acc[rp][c]);
                *(ull*)&sA[(tc*8+c)*PITCH + r0] = pk2(gelu(q.x + bv[c]), gelu(q.y + bv[c]));
            }
        }
    }
    ((float4*)sB)[tid]       = ((const float4*)g_w3T)[tid];
    ((float4*)sB)[128 + tid] = ((const float4*)g_w3T)[128 + tid];
    __syncthreads();

    // ---- layer 3 (64 -> 16): thread = 8 rows x 2 ocs ----
    {
        int rg = tid >> 3;           // 16 row-groups
        int og = tid & 7;            // oc pair {2og, 2og+1}
        ull a3[4][2];
        #pragma unroll
        for (int rp = 0; rp < 4; rp++){
            a3[rp][0] = dup2(b3[2*og]);
            a3[rp][1] = dup2(b3[2*og+1]);
        }
        #pragma unroll 4
        for (int kk = 0; kk < 64; kk++){
            ulonglong2 a01 = *(const ulonglong2*)&sA[kk*PITCH + rg*8];
            ulonglong2 a23 = *(const ulonglong2*)&sA[kk*PITCH + rg*8 + 4];
            float2 w = *(const float2*)&sB[kk*16 + 2*og];
            ull w0 = dup2(w.x), w1 = dup2(w.y);
            fma2(a3[0][0], a01.x, w0); fma2(a3[0][1], a01.x, w1);
            fma2(a3[1][0], a01.y, w0); fma2(a3[1][1], a01.y, w1);
            fma2(a3[2][0], a23.x, w0); fma2(a3[2][1], a23.x, w1);
            fma2(a3[3][0], a23.y, w0); fma2(a3[3][1], a23.y, w1);
        }
        #pragma unroll
        for (int rp = 0; rp < 4; rp++){
            float2 v0 = upk2(a3[rp][0]);
            float2 v1 = upk2(a3[rp][1]);
            #pragma unroll
            for (int lane = 0; lane < 2; lane++){
                int r = rg*8 + 2*rp + lane;
                int ii = sI[r], jj = sJ[r], bb2 = (base + r) & 1;
                float* dst = g_S + (((bb2*16 + 2*og)*512 + ii)*512 + jj);
                dst[0]       = lane ? v0.y : v0.x;
                dst[512*512] = lane ? v1.y : v1.x;
            }
        }
    }
}

// ---------------- conv1: 16->48, 3x3, pad=2, fused GELU; skip far-upper tiles ----------------
__global__ void __launch_bounds__(256) k_conv1(const float* __restrict__ cb1){
    int b  = blockIdx.z;
    int by = blockIdx.y, bx = blockIdx.x;
    if (bx >= by + 2) return;

    __shared__ float sIn[16*18*18];
    __shared__ __align__(16) float sW[16*9*48];
    int tid = threadIdx.x;

    for (int idx = tid; idx < 16*9*48/4; idx += 256)
        ((float4*)sW)[idx] = ((const float4*)g_cw1T)[idx];

    int y0 = by*16 - 2, x0 = bx*16 - 2;
    for (int idx = tid; idx < 5184; idx += 256){
        int ic = idx / 324; int rem = idx - ic*324;
        int ly = rem / 18,  lx = rem - ly*18;
        int gy = y0 + ly,   gx = x0 + lx;
        float v = 0.f;
        if ((unsigned)gy < 512u && (unsigned)gx < 512u)
            v = g_S[((b*16 + ic)*512 + gy)*512 + gx];
        sIn[idx] = v;
    }
    __syncthreads();

    int ty = tid >> 4, tx = tid & 15;
    ull acc2[12][2];
    #pragma unroll
    for (int q = 0; q < 12; q++){ acc2[q][0] = 0ull; acc2[q][1] = 0ull; }

    #pragma unroll 1
    for (int ic = 0; ic < 16; ic++){
        float v[9];
        #pragma unroll
        for (int ky = 0; ky < 3; ky++)
            #pragma unroll
            for (int kx = 0; kx < 3; kx++)
                v[ky*3+kx] = sIn[ic*324 + (ty+ky)*18 + (tx+kx)];
        #pragma unroll
        for (int tap = 0; tap < 9; tap++){
            ull vv2 = dup2(v[tap]);
            const ulonglong2* wp = (const ulonglong2*)&sW[(ic*9 + tap)*48];
            #pragma unroll
            for (int q = 0; q < 12; q++){
                ulonglong2 w4 = wp[q];
                fma2(acc2[q][0], vv2, w4.x);
                fma2(acc2[q][1], vv2, w4.y);
            }
        }
    }

    int oy = by*16 + ty, ox = bx*16 + tx;
    if (oy < 514 && ox < 514){
        #pragma unroll
        for (int q = 0; q < 12; q++){
            float4 c = *(const float4*)&cb1[q*4];
            float2 p0 = upk2(acc2[q][0]);
            float2 p1 = upk2(acc2[q][1]);
            float* dst = g_H1 + (((b*48 + q*4)*514 + oy)*514 + ox);
            dst[0]          = gelu(p0.x + c.x);
            dst[514*514]    = gelu(p0.y + c.y);
            dst[2*514*514]  = gelu(p1.x + c.z);
            dst[3*514*514]  = gelu(p1.y + c.w);
        }
    }
}

// ---------------- conv2: 48->16, 3x3 valid, + bias + lenBA scale; const fast path ----------------
__global__ void __launch_bounds__(256) k_conv2(const float* __restrict__ cb2,
                                               const float* __restrict__ cb1,
                                               float* __restrict__ out){
    int b  = blockIdx.z;
    int by = blockIdx.y, bx = blockIdx.x;
    int tid = threadIdx.x;
    int ty = tid >> 4, tx = tid & 15;
    int oy = by*16 + ty, ox = bx*16 + tx;

    if (bx >= by + 2){
        __shared__ float sKc[16];
        if (tid < 16) sKc[tid] = g_Kc[tid];
        __syncthreads();
        float scale = (float)(ox - oy);
        float* dst = out + ((oy*512 + ox)*2 + b)*16;
        #pragma unroll
        for (int q = 0; q < 4; q++){
            float4 o4;
            o4.x = scale*sKc[q*4+0];
            o4.y = scale*sKc[q*4+1];
            o4.z = scale*sKc[q*4+2];
            o4.w = scale*sKc[q*4+3];
            *(float4*)(dst + q*4) = o4;
        }
        return;
    }

    __shared__ float sIn[16*18*18];
    __shared__ __align__(16) float sW[16*9*16];
    __shared__ float sC1[48];
    if (tid < 48) sC1[tid] = gelu(cb1[tid]);
    __syncthreads();

    ull acc2[4][2];
    #pragma unroll
    for (int q = 0; q < 4; q++){ acc2[q][0] = 0ull; acc2[q][1] = 0ull; }

    for (int icc = 0; icc < 3; icc++){
        if (icc) __syncthreads();
        for (int idx = tid; idx < 2304/4; idx += 256)
            ((float4*)sW)[idx] = ((const float4*)(g_cw2T + icc*2304))[idx];
        int y0 = by*16, x0 = bx*16;
        for (int idx = tid; idx < 5184; idx += 256){
            int ic = idx / 324; int rem = idx - ic*324;
            int ly = rem / 18,  lx = rem - ly*18;
            int gy = y0 + ly,   gx = x0 + lx;
            float v = (gx >= gy + 3) ? sC1[icc*16 + ic]
                                     : g_H1[((b*48 + icc*16 + ic)*514 + gy)*514 + gx];
            sIn[idx] = v;
        }
        __syncthreads();
        #pragma unroll 1
        for (int ic = 0; ic < 16; ic++){
            float v[9];
            #pragma unroll
            for (int ky = 0; ky < 3; ky++)
                #pragma unroll
                for (int kx = 0; kx < 3; kx++)
                    v[ky*3+kx] = sIn[ic*324 + (ty+ky)*18 + (tx+kx)];
            #pragma unroll
            for (int tap = 0; tap < 9; tap++){
                ull vv2 = dup2(v[tap]);
                const ulonglong2* wp = (const ulonglong2*)&sW[(ic*9 + tap)*16];
                #pragma unroll
                for (int q = 0; q < 4; q++){
                    ulonglong2 w4 = wp[q];
                    fma2(acc2[q][0], vv2, w4.x);
                    fma2(acc2[q][1], vv2, w4.y);
                }
            }
        }
    }

    int ad = oy - ox; if (ad < 0) ad = -ad; if (ad < 1) ad = 1;
    float scale = (float)ad;
    float* dst = out + ((oy*512 + ox)*2 + b)*16;
    #pragma unroll
    for (int q = 0; q < 4; q++){
        float4 c = ((const float4*)cb2)[q];
        float2 p0 = upk2(acc2[q][0]);
        float2 p1 = upk2(acc2[q][1]);
        float4 o4;
        o4.x = scale*(p0.x + c.x);
        o4.y = scale*(p0.y + c.y);
        o4.z = scale*(p1.x + c.z);
        o4.w = scale*(p1.y + c.w);
        *(float4*)(dst + q*4) = o4;
    }
}

// ---------------- skip MLP on adjacent frames ----------------
__global__ void k_skip(const float* __restrict__ x,  const float* __restrict__ sb1,
                       const float* __restrict__ sb2, const float* __restrict__ sb3,
                       float* __restrict__ out){
    __shared__ float sIn[384], sH[64], sH2[64];
    int bid = blockIdx.x;
    int tt = bid >> 1, b = bid & 1;
    int t = threadIdx.x;
    const float* xa = x + (tt*2 + b)*128;
    const float* xb = x + ((tt+1)*2 + b)*128;
    sIn[t]       = xa[t];          sIn[64+t]  = xa[64+t];
    sIn[128+t]   = xb[t];          sIn[192+t] = xb[64+t];
    sIn[256+t]   = xa[t]*xb[t];    sIn[320+t] = xa[64+t]*xb[64+t];
    __syncthreads();
    float acc = sb1[t];
    #pragma unroll 4
    for (int k = 0; k < 384; k++) acc += sIn[k] * g_sw1T[k*64 + t];
    sH[t] = gelu(acc);
    __syncthreads();
    acc = sb2[t];
    #pragma unroll 4
    for (int k = 0; k < 64; k++) acc += sH[k] * g_sw2T[k*64 + t];
    sH2[t] = gelu(acc);
    __syncthreads();
    if (t < 16){
        float a = sb3[t];
        #pragma unroll 4
        for (int k = 0; k < 64; k++) a += sH2[k] * g_sw3T[k*16 + t];
        out[SKIP_OFF + (tt*2 + b)*16 + t] = a;
    }
}

// ---------------- launch: k_conv1 in profiled slot (our 4th launch) ----------------
extern "C" void kernel_launch(void* const* d_in, const int* in_sizes, int n_in,
                              void* d_out, int out_size){
    const float* x   = (const float*)d_in[0];
    const float* w1  = (const float*)d_in[1];
    const float* b1  = (const float*)d_in[2];
    const float* w2  = (const float*)d_in[3];
    const float* b2  = (const float*)d_in[4];
    const float* w3  = (const float*)d_in[5];
    const float* b3  = (const float*)d_in[6];
    const float* sw1 = (const float*)d_in[7];
    const float* sb1 = (const float*)d_in[8];
    const float* sw2 = (const float*)d_in[9];
    const float* sb2 = (const float*)d_in[10];
    const float* sw3 = (const float*)d_in[11];
    const float* sb3 = (const float*)d_in[12];
    const float* cw1 = (const float*)d_in[13];
    const float* cb1 = (const float*)d_in[14];
    const float* cw2 = (const float*)d_in[15];
    const float* cb2 = (const float*)d_in[16];
    float* out = (float*)d_out;

    k_init<<<dim3(192, 9), 256>>>(w1, w2, w3, sw1, sw2, sw3, cw1, cw2, x);      // 1
    k_precompute<<<dim3(1026 + ZGRID, 3), 64>>>(x, b1, cb1, cb2, cw2);          // 2
    k_pair<<<NBLK, 128>>>(x, b2, b3);                                           // 3
    k_conv1<<<dim3(33, 33, 2), 256>>>(cb1);                                     // 4 <- profiled
    k_skip<<<1022, 64>>>(x, sb1, sb2, sb3, out);                                // 5
    k_conv2<<<dim3(32, 32, 2), 256>>>(cb2, cb1, out);                           // 6
}

// round 16
// speedup vs baseline: 1.1819x; 1.1819x over previous
#include <cuda_runtime.h>

#define NN 512
#define BB 2
#define OO 16
#define CHN 48
#define H1DIM 514
#define SKIP_OFF (512*512*2*16)
#define RPB 128
#define PITCH 132
#define NBLK 2052

typedef unsigned long long ull;

// ---------------- packed f32x2 helpers (Blackwell FFMA2 via PTX) ----------------
__device__ __forceinline__ ull pk2(float lo, float hi){
    ull r; asm("mov.b64 %0, {%1,%2};" : "=l"(r) : "f"(lo), "f"(hi)); return r;
}
__device__ __forceinline__ ull dup2(float v){ return pk2(v, v); }
__device__ __forceinline__ float2 upk2(ull p){
    float2 r; asm("mov.b64 {%0,%1}, %2;" : "=f"(r.x), "=f"(r.y) : "l"(p)); return r;
}
__device__ __forceinline__ void fma2(ull &d, ull a, ull b){
    asm("fma.rn.f32x2 %0, %1, %2, %0;" : "+l"(d) : "l"(a), "l"(b));
}

// ---------------- scratch ----------------
__device__ __align__(16) float g_xc[513*256];
__device__ __align__(16) float g_x2c[513*256];
__device__ __align__(16) float g_x3c[513*256];
__device__ __align__(16) float g_w1T[768*64];
__device__ __align__(16) float g_w2T[64*64];
__device__ __align__(16) float g_w3T[64*16];
__device__ __align__(16) float g_sw1T[384*64];
__device__ __align__(16) float g_sw2T[64*64];
__device__ __align__(16) float g_sw3T[64*16];
__device__ __align__(16) float g_cw1T[16*9*48];
__device__ __align__(16) float g_cw2T[48*9*16];
__device__ __align__(16) float g_A[1024*64];
__device__ __align__(16) float g_Bv[1024*64];
__device__ __align__(16) float g_M[1026*64];
__device__ __align__(16) float g_Kc[16];
__device__ __align__(16) float g_S[BB*OO*NN*NN];
__device__ __align__(16) float g_H1[BB*CHN*H1DIM*H1DIM];

__device__ __forceinline__ float gelu(float v){
    return 0.5f*v*(1.0f + erff(0.70710678118654752440f*v));
}

// ---------------- init: 8 weight transposes + moment prefix sums ----------------
__global__ void k_init(const float* __restrict__ w1,  const float* __restrict__ w2,
                       const float* __restrict__ w3,  const float* __restrict__ sw1,
                       const float* __restrict__ sw2, const float* __restrict__ sw3,
                       const float* __restrict__ cw1, const float* __restrict__ cw2,
                       const float* __restrict__ x){
    if (blockIdx.y == 8){
        if (blockIdx.x != 0) return;
        int col = threadIdx.x;
        float c1 = 0.f, c2 = 0.f, c3 = 0.f;
        g_xc[col] = 0.f; g_x2c[col] = 0.f; g_x3c[col] = 0.f;
        for (int n0 = 0; n0 < NN; n0 += 8){
            float buf[8];
            #pragma unroll
            for (int u = 0; u < 8; u++) buf[u] = x[(n0+u)*256 + col];
            #pragma unroll
            for (int u = 0; u < 8; u++){
                float v = buf[u];
                c1 += v; c2 += v*v; c3 += v*v*v;
                int r = (n0+u+1)*256 + col;
                g_xc[r] = c1; g_x2c[r] = c2; g_x3c[r] = c3;
            }
        }
        return;
    }
    const float* src; float* dst; int Osz, Ksz;
    switch(blockIdx.y){
        case 0: src = w1;  dst = g_w1T;  Osz = 64; Ksz = 768; break;
        case 1: src = w2;  dst = g_w2T;  Osz = 64; Ksz = 64;  break;
        case 2: src = w3;  dst = g_w3T;  Osz = 16; Ksz = 64;  break;
        case 3: src = sw1; dst = g_sw1T; Osz = 64; Ksz = 384; break;
        case 4: src = sw2; dst = g_sw2T; Osz = 64; Ksz = 64;  break;
        case 5: src = sw3; dst = g_sw3T; Osz = 16; Ksz = 64;  break;
        case 6: src = cw1; dst = g_cw1T; Osz = 48; Ksz = 144; break;
        default:src = cw2; dst = g_cw2T; Osz = 16; Ksz = 432; break;
    }
    int idx = blockIdx.x*blockDim.x + threadIdx.x;
    if (idx < Osz*Ksz){
        int o = idx / Ksz, k = idx - o*Ksz;
        dst[k*Osz + o] = src[idx];
    }
}

// ---------------- separable layer-1 precomputes + fused S-zeroing + Kc ----------------
#define ZGRID 2048
__global__ void k_precompute(const float* __restrict__ x, const float* __restrict__ b1,
                             const float* __restrict__ cb1, const float* __restrict__ cb2,
                             const float* __restrict__ cw2){
    int type = blockIdx.y;
    int rid  = blockIdx.x;
    int t    = threadIdx.x;
    if (rid >= 1026){
        int zid = ((rid-1026)*3 + type)*64 + t;
        const int total4 = BB*OO*NN*NN/4;
        for (int i = zid; i < total4; i += ZGRID*3*64)
            ((float4*)g_S)[i] = make_float4(0.f,0.f,0.f,0.f);
        if (type == 2 && rid == 1026 && t < 16){
            float kc = cb2[t];
            for (int ic = 0; ic < 48; ic++){
                float c1v = gelu(cb1[ic]);
                #pragma unroll
                for (int k = 0; k < 9; k++)
                    kc += cw2[t*432 + ic*9 + k] * c1v;
            }
            g_Kc[t] = kc;
        }
        return;
    }
    __shared__ float sIn[384];
    if (type < 2){
        if (rid >= 1024) return;
        const float* xr = x + rid*128;
        sIn[t] = xr[t]; sIn[64+t] = xr[64+t];
        __syncthreads();
        float acc = (type == 0) ? b1[t] : 0.f;
        const float* w = g_w1T + (type == 0 ? 0 : 128)*64 + t;
        #pragma unroll 4
        for (int d = 0; d < 128; d++) acc += sIn[d] * w[d*64];
        (type == 0 ? g_A : g_Bv)[rid*64 + t] = acc;
    } else {
        const float* c1 = g_xc  + rid*128;
        const float* c2 = g_x2c + rid*128;
        const float* c3 = g_x3c + rid*128;
        sIn[t]       = c1[t]; sIn[64+t]  = c1[64+t];
        sIn[128+t]   = c2[t]; sIn[192+t] = c2[64+t];
        sIn[256+t]   = c3[t]; sIn[320+t] = c3[64+t];
        __syncthreads();
        float acc = 0.f;
        #pragma unroll 4
        for (int d = 0; d < 128; d++){
            acc += sIn[d]       * g_w1T[(384+d)*64 + t];
            acc += sIn[128 + d] * g_w1T[(512+d)*64 + t];
            acc += sIn[256 + d] * g_w1T[(640+d)*64 + t];
        }
        g_M[rid*64 + t] = acc;
    }
}

// ---------------- pair MLP: 128x64 tile, 256 threads, 8x4 per thread (R14-proven) ----------------
__global__ void __launch_bounds__(256) k_pair(const float* __restrict__ x,
                                              const float* __restrict__ b2,
                                              const float* __restrict__ b3){
    __shared__ __align__(16) float sA[64*PITCH];
    __shared__ __align__(16) float sB[32*64];
    __shared__ int   sI[RPB], sJ[RPB];
    __shared__ float sInvL[RPB];

    int tid  = threadIdx.x;
    int base = blockIdx.x * RPB;

    if (tid < RPB){
        int m = base + tid;
        int p = m >> 1;
        int i = (int)floorf((sqrtf(8.0f*(float)p + 1.0f) - 1.0f) * 0.5f);
        while ((i+1)*(i+2)/2 <= p) i++;
        while (i*(i+1)/2 > p)      i--;
        int j = p - i*(i+1)/2;
        sI[tid] = i; sJ[tid] = j;
        sInvL[tid] = 1.0f / (float)(i - j + 1);
    }
    __syncthreads();

    int tr = tid >> 4, tc = tid & 15;
    ull acc[4][4];
    #pragma unroll
    for (int a = 0; a < 4; a++)
        #pragma unroll
        for (int c = 0; c < 4; c++) acc[a][c] = 0ull;

    int srow = tid >> 1, dg = tid & 1;
    int sbb  = (base + srow) & 1;
    const float* xi = x + (sI[srow]*2 + sbb)*128;
    const float* xj = x + (sJ[srow]*2 + sbb)*128;

    for (int kc = 0; kc < 2; kc++){
        if (kc) __syncthreads();
        #pragma unroll
        for (int q = 0; q < 8; q++){
            int dd = kc*64 + dg*32 + q*4;
            float4 a4 = *(const float4*)(xi + dd);
            float4 c4 = *(const float4*)(xj + dd);
            int kk = dg*32 + q*4;
            sA[(kk+0)*PITCH + srow] = a4.x*c4.x;
            sA[(kk+1)*PITCH + srow] = a4.y*c4.y;
            sA[(kk+2)*PITCH + srow] = a4.z*c4.z;
            sA[(kk+3)*PITCH + srow] = a4.w*c4.w;
        }
        for (int sub = 0; sub < 2; sub++){
            __syncthreads();
            {
                const float4* src = (const float4*)(g_w1T + (256 + kc*64 + sub*32)*64);
                ((float4*)sB)[tid]       = src[tid];
                ((float4*)sB)[256 + tid] = src[256 + tid];
            }
            __syncthreads();
            #pragma unroll 4
            for (int k2 = 0; k2 < 32; k2++){
                int kk = sub*32 + k2;
                ulonglong2 a01 = *(const ulonglong2*)&sA[kk*PITCH + tr*8];
                ulonglong2 a23 = *(const ulonglong2*)&sA[kk*PITCH + tr*8 + 4];
                float4 b4 = *(const float4*)&sB[k2*64 + tc*4];
                ull ub0 = dup2(b4.x), ub1 = dup2(b4.y), ub2 = dup2(b4.z), ub3 = dup2(b4.w);
                fma2(acc[0][0], a01.x, ub0); fma2(acc[0][1], a01.x, ub1);
                fma2(acc[0][2], a01.x, ub2); fma2(acc[0][3], a01.x, ub3);
                fma2(acc[1][0], a01.y, ub0); fma2(acc[1][1], a01.y, ub1);
                fma2(acc[1][2], a01.y, ub2); fma2(acc[1][3], a01.y, ub3);
                fma2(acc[2][0], a23.x, ub0); fma2(acc[2][1], a23.x, ub1);
                fma2(acc[2][2], a23.x, ub2); fma2(acc[2][3], a23.x, ub3);
                fma2(acc[3][0], a23.y, ub0); fma2(acc[3][1], a23.y, ub1);
                fma2(acc[3][2], a23.y, ub2); fma2(acc[3][3], a23.y, ub3);
            }
        }
    }
    __syncthreads();

    #pragma unroll
    for (int rp = 0; rp < 4; rp++){
        int r0 = tr*8 + 2*rp;
        float v0[4], v1[4];
        #pragma unroll
        for (int lane = 0; lane < 2; lane++){
            int r = r0 + lane;
            int ii = sI[r], jj = sJ[r];
            int bb2 = (base + r) & 1;
            float il = sInvL[r];
            float4 pa = *(const float4*)(g_A  + (ii*2+bb2)*64 + tc*4);
            float4 pb = *(const float4*)(g_Bv + (jj*2+bb2)*64 + tc*4);
            float4 m1 = *(const float4*)(g_M  + ((ii+1)*2+bb2)*64 + tc*4);
            float4 m0 = *(const float4*)(g_M  + (jj*2+bb2)*64 + tc*4);
            float pre0 = pa.x + pb.x + il*(m1.x - m0.x);
            float pre1 = pa.y + pb.y + il*(m1.y - m0.y);
            float pre2 = pa.z + pb.z + il*(m1.z - m0.z);
            float pre3 = pa.w + pb.w + il*(m1.w - m0.w);
            float* vv = lane ? v1 : v0;
            float2 q0 = upk2(acc[rp][0]); float2 q1 = upk2(acc[rp][1]);
            float2 q2 = upk2(acc[rp][2]); float2 q3 = upk2(acc[rp][3]);
            vv[0] = gelu((lane ? q0.y : q0.x) + pre0);
            vv[1] = gelu((lane ? q1.y : q1.x) + pre1);
            vv[2] = gelu((lane ? q2.y : q2.x) + pre2);
            vv[3] = gelu((lane ? q3.y : q3.x) + pre3);
        }
        #pragma unroll
        for (int c = 0; c < 4; c++){
            *(ull*)&sA[(tc*4+c)*PITCH + r0] = pk2(v0[c], v1[c]);
            acc[rp][c] = 0ull;
        }
    }

    for (int sub = 0; sub < 2; sub++){
        __syncthreads();
        {
            const float4* src = (const float4*)(g_w2T + sub*32*64);
            ((float4*)sB)[tid]       = src[tid];
            ((float4*)sB)[256 + tid] = src[256 + tid];
        }
        __syncthreads();
        #pragma unroll 4
        for (int k2 = 0; k2 < 32; k2++){
            int kk = sub*32 + k2;
            ulonglong2 a01 = *(const ulonglong2*)&sA[kk*PITCH + tr*8];
            ulonglong2 a23 = *(const ulonglong2*)&sA[kk*PITCH + tr*8 + 4];
            float4 b4 = *(const float4*)&sB[k2*64 + tc*4];
            ull ub0 = dup2(b4.x), ub1 = dup2(b4.y), ub2 = dup2(b4.z), ub3 = dup2(b4.w);
            fma2(acc[0][0], a01.x, ub0); fma2(acc[0][1], a01.x, ub1);
            fma2(acc[0][2], a01.x, ub2); fma2(acc[0][3], a01.x, ub3);
            fma2(acc[1][0], a01.y, ub0); fma2(acc[1][1], a01.y, ub1);
            fma2(acc[1][2], a01.y, ub2); fma2(acc[1][3], a01.y, ub3);
            fma2(acc[2][0], a23.x, ub0); fma2(acc[2][1], a23.x, ub1);
            fma2(acc[2][2], a23.x, ub2); fma2(acc[2][3], a23.x, ub3);
            fma2(acc[3][0], a23.y, ub0); fma2(acc[3][1], a23.y, ub1);
            fma2(acc[3][2], a23.y, ub2); fma2(acc[3][3], a23.y, ub3);
        }
    }
    __syncthreads();

    {
        float4 bv = *(const float4*)(b2 + tc*4);
        #pragma unroll
        for (int rp = 0; rp < 4; rp++){
            int r0 = tr*8 + 2*rp;
            float2 q0 = upk2(acc[rp][0]); float2 q1 = upk2(acc[rp][1]);
            float2 q2 = upk2(acc[rp][2]); float2 q3 = upk2(acc[rp][3]);
            *(ull*)&sA[(tc*4+0)*PITCH + r0] = pk2(gelu(q0.x + bv.x), gelu(q0.y + bv.x));
            *(ull*)&sA[(tc*4+1)*PITCH + r0] = pk2(gelu(q1.x + bv.y), gelu(q1.y + bv.y));
            *(ull*)&sA[(tc*4+2)*PITCH + r0] = pk2(gelu(q2.x + bv.z), gelu(q2.y + bv.z));
            *(ull*)&sA[(tc*4+3)*PITCH + r0] = pk2(gelu(q3.x + bv.w), gelu(q3.y + bv.w));
        }
    }
    ((float4*)sB)[tid] = ((const float4*)g_w3T)[tid];
    __syncthreads();

    int r3 = tid >> 1;
    int og = (tid & 1) * 8;
    ull o[4];
    #pragma unroll
    for (int p = 0; p < 4; p++) o[p] = pk2(b3[og + 2*p], b3[og + 2*p + 1]);
    #pragma unroll 8
    for (int kk = 0; kk < 64; kk++){
        ull av = dup2(sA[kk*PITCH + r3]);
        ulonglong2 w0 = *(const ulonglong2*)&sB[kk*16 + og];
        ulonglong2 w1 = *(const ulonglong2*)&sB[kk*16 + og + 4];
        fma2(o[0], av, w0.x); fma2(o[1], av, w0.y);
        fma2(o[2], av, w1.x); fma2(o[3], av, w1.y);
    }
    int ii = sI[r3], jj = sJ[r3], bb2 = (base + r3) & 1;
    float* dst = g_S + (((bb2*16 + og)*512 + ii)*512 + jj);
    #pragma unroll
    for (int p = 0; p < 4; p++){
        float2 v = upk2(o[p]);
        dst[(2*p)  *512*512] = v.x;
        dst[(2*p+1)*512*512] = v.y;
    }
}

// ---------------- conv1: 16->48, 3x3, pad=2; 2x2 pixels x 12 ocs per thread ----------------
__global__ void __launch_bounds__(256) k_conv1(const float* __restrict__ cb1){
    int b  = blockIdx.z;
    int by = blockIdx.y, bx = blockIdx.x;
    if (bx >= by + 2) return;

    __shared__ float sIn[16*324];                // 18x18 per ic
    __shared__ __align__(16) float sW[16*9*48];
    int tid = threadIdx.x;

    for (int idx = tid; idx < 16*9*48/4; idx += 256)
        ((float4*)sW)[idx] = ((const float4*)g_cw1T)[idx];

    int y0 = by*16 - 2, x0 = bx*16 - 2;
    for (int idx = tid; idx < 5184; idx += 256){
        int ic = idx / 324; int rem = idx - ic*324;
        int ly = rem / 18,  lx = rem - ly*18;
        int gy = y0 + ly,   gx = x0 + lx;
        float v = 0.f;
        if ((unsigned)gy < 512u && (unsigned)gx < 512u)
            v = g_S[((b*16 + ic)*512 + gy)*512 + gx];
        sIn[idx] = v;
    }
    __syncthreads();

    int ocg = tid >> 6;                  // 4 groups x 12 ocs
    int pg  = tid & 63;
    int py  = pg >> 3, px = pg & 7;      // 2x2 pixel block at (py*2, px*2)

    ull acc[2][2][6];
    #pragma unroll
    for (int dy = 0; dy < 2; dy++)
        #pragma unroll
        for (int dx = 0; dx < 2; dx++)
            #pragma unroll
            for (int p = 0; p < 6; p++) acc[dy][dx][p] = 0ull;

    #pragma unroll 1
    for (int ic = 0; ic < 16; ic++){
        float v[4][4];
        #pragma unroll
        for (int r = 0; r < 4; r++){
            const float* rowp = &sIn[ic*324 + (py*2+r)*18 + px*2];
            float2 lo = *(const float2*)rowp;
            float2 hi = *(const float2*)(rowp + 2);
            v[r][0] = lo.x; v[r][1] = lo.y; v[r][2] = hi.x; v[r][3] = hi.y;
        }
        #pragma unroll
        for (int tap = 0; tap < 9; tap++){
            int ky = tap / 3, kx = tap - ky*3;
            const float* wp = &sW[(ic*9 + tap)*48 + ocg*12];
            ulonglong2 w0 = *(const ulonglong2*)wp;
            ulonglong2 w1 = *(const ulonglong2*)(wp + 4);
            ulonglong2 w2 = *(const ulonglong2*)(wp + 8);
            #pragma unroll
            for (int dy = 0; dy < 2; dy++)
                #pragma unroll
                for (int dx = 0; dx < 2; dx++){
                    ull vv = dup2(v[dy+ky][dx+kx]);
                    fma2(acc[dy][dx][0], vv, w0.x);
                    fma2(acc[dy][dx][1], vv, w0.y);
                    fma2(acc[dy][dx][2], vv, w1.x);
                    fma2(acc[dy][dx][3], vv, w1.y);
                    fma2(acc[dy][dx][4], vv, w2.x);
                    fma2(acc[dy][dx][5], vv, w2.y);
                }
        }
    }

    float cbv[12];
    #pragma unroll
    for (int p = 0; p < 12; p++) cbv[p] = cb1[ocg*12 + p];

    int oyb = by*16 + py*2, oxb = bx*16 + px*2;
    #pragma unroll
    for (int dy = 0; dy < 2; dy++){
        int oy = oyb + dy;
        if (oy >= 514) continue;
        #pragma unroll
        for (int dx = 0; dx < 2; dx++){
            int ox = oxb + dx;
            if (ox >= 514) continue;
            float* dst = g_H1 + (((ull)(b*48 + ocg*12))*514 + oy)*514 + ox;
            #pragma unroll
            for (int p = 0; p < 6; p++){
                float2 q = upk2(acc[dy][dx][p]);
                dst[(2*p)  *514*514] = gelu(q.x + cbv[2*p]);
                dst[(2*p+1)*514*514] = gelu(q.y + cbv[2*p+1]);
            }
        }
    }
}

// ---------------- conv2: 48->16, 3x3 valid; 2x2 pixels x 4 ocs per thread ----------------
__global__ void __launch_bounds__(256) k_conv2(const float* __restrict__ cb2,
                                               const float* __restrict__ cb1,
                                               float* __restrict__ out){
    int b  = blockIdx.z;
    int by = blockIdx.y, bx = blockIdx.x;
    int tid = threadIdx.x;
    int ocg = tid >> 6;                 // 4 groups x 4 ocs
    int pg  = tid & 63;
    int py  = pg >> 3, px = pg & 7;
    int oyb = by*16 + py*2, oxb = bx*16 + px*2;

    if (bx >= by + 2){
        __shared__ float sKc[16];
        if (tid < 16) sKc[tid] = g_Kc[tid];
        __syncthreads();
        float4 kc = *(const float4*)&sKc[ocg*4];
        #pragma unroll
        for (int dy = 0; dy < 2; dy++)
            #pragma unroll
            for (int dx = 0; dx < 2; dx++){
                int oy = oyb + dy, ox = oxb + dx;
                float scale = (float)(ox - oy);
                float4 o4 = make_float4(scale*kc.x, scale*kc.y, scale*kc.z, scale*kc.w);
                *(float4*)(out + ((oy*512 + ox)*2 + b)*16 + ocg*4) = o4;
            }
        return;
    }

    __shared__ float sIn[16*324];
    __shared__ __align__(16) float sW[16*9*16];
    __shared__ float sC1[48];
    if (tid < 48) sC1[tid] = gelu(cb1[tid]);

    ull acc[2][2][2];
    #pragma unroll
    for (int dy = 0; dy < 2; dy++)
        #pragma unroll
        for (int dx = 0; dx < 2; dx++){ acc[dy][dx][0] = 0ull; acc[dy][dx][1] = 0ull; }

    for (int icc = 0; icc < 3; icc++){
        __syncthreads();
        for (int idx = tid; idx < 2304/4; idx += 256)
            ((float4*)sW)[idx] = ((const float4*)(g_cw2T + icc*2304))[idx];
        int y0 = by*16, x0 = bx*16;
        for (int idx = tid; idx < 5184; idx += 256){
            int ic = idx / 324; int rem = idx - ic*324;
            int ly = rem / 18,  lx = rem - ly*18;
            int gy = y0 + ly,   gx = x0 + lx;
            float v = (gx >= gy + 3) ? sC1[icc*16 + ic]
                                     : g_H1[(((ull)(b*48 + icc*16 + ic))*514 + gy)*514 + gx];
            sIn[idx] = v;
        }
        __syncthreads();
        #pragma unroll 1
        for (int ic = 0; ic < 16; ic++){
            float v[4][4];
            #pragma unroll
            for (int r = 0; r < 4; r++){
                const float* rowp = &sIn[ic*324 + (py*2+r)*18 + px*2];
                float2 lo = *(const float2*)rowp;
                float2 hi = *(const float2*)(rowp + 2);
                v[r][0] = lo.x; v[r][1] = lo.y; v[r][2] = hi.x; v[r][3] = hi.y;
            }
            #pragma unroll
            for (int tap = 0; tap < 9; tap++){
                int ky = tap / 3, kx = tap - ky*3;
                ulonglong2 w = *(const ulonglong2*)&sW[(ic*9 + tap)*16 + ocg*4];
                #pragma unroll
                for (int dy = 0; dy < 2; dy++)
                    #pragma unroll
                    for (int dx = 0; dx < 2; dx++){
                        ull vv = dup2(v[dy+ky][dx+kx]);
                        fma2(acc[dy][dx][0], vv, w.x);
                        fma2(acc[dy][dx][1], vv, w.y);
                    }
            }
        }
    }

    float4 cbv = *(const float4*)&cb2[ocg*4];
    #pragma unroll
    for (int dy = 0; dy < 2; dy++)
        #pragma unroll
        for (int dx = 0; dx < 2; dx++){
            int oy = oyb + dy, ox = oxb + dx;
            int ad = oy - ox; if (ad < 0) ad = -ad; if (ad < 1) ad = 1;
            float scale = (float)ad;
            float2 q0 = upk2(acc[dy][dx][0]);
            float2 q1 = upk2(acc[dy][dx][1]);
            float4 o4;
            o4.x = scale*(q0.x + cbv.x);
            o4.y = scale*(q0.y + cbv.y);
            o4.z = scale*(q1.x + cbv.z);
            o4.w = scale*(q1.y + cbv.w);
            *(float4*)(out + ((oy*512 + ox)*2 + b)*16 + ocg*4) = o4;
        }
}

// ---------------- skip MLP on adjacent frames ----------------
__global__ void k_skip(const float* __restrict__ x,  const float* __restrict__ sb1,
                       const float* __restrict__ sb2, const float* __restrict__ sb3,
                       float* __restrict__ out){
    __shared__ float sIn[384], sH[64], sH2[64];
    int bid = blockIdx.x;
    int tt = bid >> 1, b = bid & 1;
    int t = threadIdx.x;
    const float* xa = x + (tt*2 + b)*128;
    const float* xb = x + ((tt+1)*2 + b)*128;
    sIn[t]       = xa[t];          sIn[64+t]  = xa[64+t];
    sIn[128+t]   = xb[t];          sIn[192+t] = xb[64+t];
    sIn[256+t]   = xa[t]*xb[t];    sIn[320+t] = xa[64+t]*xb[64+t];
    __syncthreads();
    float acc = sb1[t];
    #pragma unroll 4
    for (int k = 0; k < 384; k++) acc += sIn[k] * g_sw1T[k*64 + t];
    sH[t] = gelu(acc);
    __syncthreads();
    acc = sb2[t];
    #pragma unroll 4
    for (int k = 0; k < 64; k++) acc += sH[k] * g_sw2T[k*64 + t];
    sH2[t] = gelu(acc);
    __syncthreads();
    if (t < 16){
        float a = sb3[t];
        #pragma unroll 4
        for (int k = 0; k < 64; k++) a += sH2[k] * g_sw3T[k*16 + t];
        out[SKIP_OFF + (tt*2 + b)*16 + t] = a;
    }
}

// ---------------- launch: k_conv1 in profiled slot (our 4th launch) ----------------
extern "C" void kernel_launch(void* const* d_in, const int* in_sizes, int n_in,
                              void* d_out, int out_size){
    const float* x   = (const float*)d_in[0];
    const float* w1  = (const float*)d_in[1];
    const float* b1  = (const float*)d_in[2];
    const float* w2  = (const float*)d_in[3];
    const float* b2  = (const float*)d_in[4];
    const float* w3  = (const float*)d_in[5];
    const float* b3  = (const float*)d_in[6];
    const float* sw1 = (const float*)d_in[7];
    const float* sb1 = (const float*)d_in[8];
    const float* sw2 = (const float*)d_in[9];
    const float* sb2 = (const float*)d_in[10];
    const float* sw3 = (const float*)d_in[11];
    const float* sb3 = (const float*)d_in[12];
    const float* cw1 = (const float*)d_in[13];
    const float* cb1 = (const float*)d_in[14];
    const float* cw2 = (const float*)d_in[15];
    const float* cb2 = (const float*)d_in[16];
    float* out = (float*)d_out;

    k_init<<<dim3(192, 9), 256>>>(w1, w2, w3, sw1, sw2, sw3, cw1, cw2, x);      // 1
    k_precompute<<<dim3(1026 + ZGRID, 3), 64>>>(x, b1, cb1, cb2, cw2);          // 2
    k_pair<<<NBLK, 256>>>(x, b2, b3);                                           // 3
    k_conv1<<<dim3(33, 33, 2), 256>>>(cb1);                                     // 4 <- profiled
    k_skip<<<1022, 64>>>(x, sb1, sb2, sb3, out);                                // 5
    k_conv2<<<dim3(32, 32, 2), 256>>>(cb2, cb1, out);                           // 6
}